// round 11
// baseline (speedup 1.0000x reference)
#include <cuda_runtime.h>
#include <cuda_fp16.h>
#include <math.h>
#include <stdint.h>

#define BB 512
#define TT 2048
#define DD 20
#define C0 32
#define C1 16
#define CH 256
#define NCHUNK ((BB*TT)/CH)     /* 4096 */
#define NTOT   ((double)(BB)*(double)(TT))

typedef unsigned long long u64;

// ---------------- scratch (device globals; no allocation) ----------------
__device__ uint4  g_h0h[(size_t)NCHUNK * 8 * 4 * 32];  // fp16 h0, 67MB
__device__ uint4  g_h1h[(size_t)NCHUNK * 8 * 2 * 32];  // fp16 h1, 33.5MB
__device__ float  g_Weff[BB * DD * C0];            // [b][d][c]
__device__ float  g_Cb[BB * C0];                   // [b][c]
__device__ double g_stats[96];                     // [0:32) s0 [32:64) q0 [64:80) s1 [80:96) q1
__device__ float4 g_dice0[C0];                     // {mean, rstd, alpha, 1-alpha} (for dice_f)

#define F4Z make_float4(0.f,0.f,0.f,0.f)
#define SHRED(vv_) {for(int o_=16;o_>0;o_>>=1){vv_.x+=__shfl_xor_sync(0xffffffffu,vv_.x,o_);vv_.y+=__shfl_xor_sync(0xffffffffu,vv_.y,o_);vv_.z+=__shfl_xor_sync(0xffffffffu,vv_.z,o_);vv_.w+=__shfl_xor_sync(0xffffffffu,vv_.w,o_);}}

// ---- packed f32x2 primitives ----
__device__ __forceinline__ u64 pack2(float lo, float hi) {
    u64 r; asm("mov.b64 %0, {%1, %2};" : "=l"(r) : "f"(lo), "f"(hi)); return r;
}
__device__ __forceinline__ void unpack2(u64 v, float& lo, float& hi) {
    asm("mov.b64 {%0, %1}, %2;" : "=f"(lo), "=f"(hi) : "l"(v));
}
__device__ __forceinline__ void fma2(u64& acc, u64 a, u64 b) {
    asm("fma.rn.f32x2 %0, %1, %2, %0;" : "+l"(acc) : "l"(a), "l"(b));
}
__device__ __forceinline__ void add2(u64& acc, u64 a) {
    asm("add.rn.f32x2 %0, %1, %0;" : "+l"(acc) : "l"(a));
}
__device__ __forceinline__ uint32_t h2p(u64 v) {
    float lo, hi; unpack2(v, lo, hi);
    union { __half2 h; uint32_t u; } cv;
    cv.h = __floats2half2_rn(lo, hi);
    return cv.u;
}
__device__ __forceinline__ float2 upkh(uint32_t u) {
    union { __half2 h; uint32_t u; } cv;
    cv.u = u;
    return __half22float2(cv.h);
}

// classic dice (proven in k_h1): pr = {mean, rstd, alpha, 1-alpha}
__device__ __forceinline__ float dice_f(float x, float4 pr) {
    float xn = (x - pr.x) * pr.y;
    float p  = 1.0f / (1.0f + __expf(-xn));
    return x * (pr.z + p * pr.w);
}

// folded fast dice (proven in k_out): pr = {c1, c0, alpha, 1-alpha}
__device__ __forceinline__ float dice_fast(float x, float4 pr) {
    float t = fmaf(x, pr.x, pr.y);
    float e; asm("ex2.approx.f32 %0, %1;" : "=f"(e) : "f"(t));
    float d = 1.0f + e;
    float p; asm("rcp.approx.f32 %0, %1;" : "=f"(p) : "f"(d));
    return x * fmaf(p, pr.w, pr.z);
}

#define LOG2E 1.442695040888963f

// stage one 256x20 key chunk into padded smem (row stride 21 -> conflict-free)
__device__ __forceinline__ void stage_keys(float* sK, const float* __restrict__ keys,
                                           size_t chunk, int tid) {
    const float4* src = (const float4*)(keys + chunk * (size_t)(CH * DD));
#pragma unroll
    for (int i = 0; i < 5; i++) {
        float4 t = src[tid + i * CH];
        int f = tid + i * CH;
        int r = f / 5;
        int c = (f - r * 5) * 4;
        float* p = &sK[r * 21 + c];
        p[0] = t.x; p[1] = t.y; p[2] = t.z; p[3] = t.w;
    }
}

// ---------------- K0: per-batch folded weights + zero accumulators ----------------
__global__ void k_prep(const float* __restrict__ q, const float* __restrict__ W0,
                       const float* __restrict__ b0, float* __restrict__ out) {
    int b = blockIdx.x;
    int c = threadIdx.x;              // 32 threads
    if (b == 0) {
        for (int i = c; i < 96; i += 32) g_stats[i] = 0.0;
    }
    int gid = b * 32 + c;
    if (gid < BB * DD) out[gid] = 0.0f;

    float acc = b0[c];
#pragma unroll
    for (int d = 0; d < DD; d++) {
        float qd = q[b * DD + d];
        float wA = W0[(d)          * C0 + c];
        float wB = W0[(DD + d)     * C0 + c];
        float wC = W0[(2 * DD + d) * C0 + c];
        float wD = W0[(3 * DD + d) * C0 + c];
        g_Weff[(b * DD + d) * C0 + c] = wB - wC + qd * wD;
        acc += qd * (wA + wC);
    }
    g_Cb[b * C0 + c] = acc;
}

// ---------------- K1: h0 = keys @ Weff[b] + Cb[b]; store fp16 + stats ----------------
// grid 2048: 4 blocks per batch, 2 chunks each (finer tasks -> less wave quantization)
__global__ void __launch_bounds__(CH, 2) k_h0(const float* __restrict__ keys) {
    int blk = blockIdx.x;
    int b   = blk >> 2;
    int ck0 = (blk & 3) * 2;
    int tid = threadIdx.x;
    int lane = tid & 31, warp = tid >> 5;

    __shared__ float4 sW[DD * 8];
    __shared__ float4 sC[8];
    __shared__ float  sK[CH * 21];
    __shared__ float4 sRed[8 * 16];

    for (int i = tid; i < DD * 8; i += CH)
        sW[i] = ((const float4*)(&g_Weff[b * DD * C0]))[i];
    if (tid < 8)
        sC[tid] = ((const float4*)(&g_Cb[b * C0]))[tid];

    const ulonglong2* sW2 = (const ulonglong2*)sW;
    const ulonglong2* sC2 = (const ulonglong2*)sC;

    u64 s0=0,s1=0,s2=0,s3=0,s4=0,s5=0,s6=0,s7=0,s8=0,s9=0,s10=0,s11=0,s12=0,s13=0,s14=0,s15=0;
    u64 q0=0,q1=0,q2=0,q3=0,q4=0,q5=0,q6=0,q7=0,q8=0,q9=0,q10=0,q11=0,q12=0,q13=0,q14=0,q15=0;

    for (int lc = 0; lc < 2; lc++) {
        size_t chunk = (size_t)b * 8 + ck0 + lc;
        __syncthreads();
        stage_keys(sK, keys, chunk, tid);
        __syncthreads();

        u64 a0,a1,a2,a3,a4,a5,a6,a7,a8,a9,a10,a11,a12,a13,a14,a15;
        { ulonglong2 t;
          t=sC2[0]; a0 =t.x; a1 =t.y;  t=sC2[1]; a2 =t.x; a3 =t.y;
          t=sC2[2]; a4 =t.x; a5 =t.y;  t=sC2[3]; a6 =t.x; a7 =t.y;
          t=sC2[4]; a8 =t.x; a9 =t.y;  t=sC2[5]; a10=t.x; a11=t.y;
          t=sC2[6]; a12=t.x; a13=t.y;  t=sC2[7]; a14=t.x; a15=t.y; }

#pragma unroll
        for (int d = 0; d < DD; d++) {
            float kd = sK[tid * 21 + d];
            u64 kdd = pack2(kd, kd);
            ulonglong2 w;
            w=sW2[d*8+0]; fma2(a0 ,w.x,kdd); fma2(a1 ,w.y,kdd);
            w=sW2[d*8+1]; fma2(a2 ,w.x,kdd); fma2(a3 ,w.y,kdd);
            w=sW2[d*8+2]; fma2(a4 ,w.x,kdd); fma2(a5 ,w.y,kdd);
            w=sW2[d*8+3]; fma2(a6 ,w.x,kdd); fma2(a7 ,w.y,kdd);
            w=sW2[d*8+4]; fma2(a8 ,w.x,kdd); fma2(a9 ,w.y,kdd);
            w=sW2[d*8+5]; fma2(a10,w.x,kdd); fma2(a11,w.y,kdd);
            w=sW2[d*8+6]; fma2(a12,w.x,kdd); fma2(a13,w.y,kdd);
            w=sW2[d*8+7]; fma2(a14,w.x,kdd); fma2(a15,w.y,kdd);
        }
        uint4 p0 = make_uint4(h2p(a0), h2p(a1), h2p(a2), h2p(a3));
        uint4 p1 = make_uint4(h2p(a4), h2p(a5), h2p(a6), h2p(a7));
        uint4 p2 = make_uint4(h2p(a8), h2p(a9), h2p(a10), h2p(a11));
        uint4 p3 = make_uint4(h2p(a12), h2p(a13), h2p(a14), h2p(a15));
        uint4* dst = &g_h0h[chunk * 1024 + warp * 128];
        __stcs(&dst[0*32+lane], p0); __stcs(&dst[1*32+lane], p1);
        __stcs(&dst[2*32+lane], p2); __stcs(&dst[3*32+lane], p3);

        add2(s0,a0); add2(s1,a1); add2(s2,a2); add2(s3,a3);
        add2(s4,a4); add2(s5,a5); add2(s6,a6); add2(s7,a7);
        add2(s8,a8); add2(s9,a9); add2(s10,a10); add2(s11,a11);
        add2(s12,a12); add2(s13,a13); add2(s14,a14); add2(s15,a15);
        fma2(q0,a0,a0); fma2(q1,a1,a1); fma2(q2,a2,a2); fma2(q3,a3,a3);
        fma2(q4,a4,a4); fma2(q5,a5,a5); fma2(q6,a6,a6); fma2(q7,a7,a7);
        fma2(q8,a8,a8); fma2(q9,a9,a9); fma2(q10,a10,a10); fma2(q11,a11,a11);
        fma2(q12,a12,a12); fma2(q13,a13,a13); fma2(q14,a14,a14); fma2(q15,a15,a15);
    }

    float4 S0,S1,S2,S3,S4,S5,S6,S7, Q0,Q1,Q2,Q3,Q4,Q5,Q6,Q7;
    unpack2(s0,S0.x,S0.y); unpack2(s1,S0.z,S0.w);  unpack2(s2,S1.x,S1.y); unpack2(s3,S1.z,S1.w);
    unpack2(s4,S2.x,S2.y); unpack2(s5,S2.z,S2.w);  unpack2(s6,S3.x,S3.y); unpack2(s7,S3.z,S3.w);
    unpack2(s8,S4.x,S4.y); unpack2(s9,S4.z,S4.w);  unpack2(s10,S5.x,S5.y); unpack2(s11,S5.z,S5.w);
    unpack2(s12,S6.x,S6.y); unpack2(s13,S6.z,S6.w); unpack2(s14,S7.x,S7.y); unpack2(s15,S7.z,S7.w);
    unpack2(q0,Q0.x,Q0.y); unpack2(q1,Q0.z,Q0.w);  unpack2(q2,Q1.x,Q1.y); unpack2(q3,Q1.z,Q1.w);
    unpack2(q4,Q2.x,Q2.y); unpack2(q5,Q2.z,Q2.w);  unpack2(q6,Q3.x,Q3.y); unpack2(q7,Q3.z,Q3.w);
    unpack2(q8,Q4.x,Q4.y); unpack2(q9,Q4.z,Q4.w);  unpack2(q10,Q5.x,Q5.y); unpack2(q11,Q5.z,Q5.w);
    unpack2(q12,Q6.x,Q6.y); unpack2(q13,Q6.z,Q6.w); unpack2(q14,Q7.x,Q7.y); unpack2(q15,Q7.z,Q7.w);

    SHRED(S0); SHRED(S1); SHRED(S2); SHRED(S3);
    SHRED(S4); SHRED(S5); SHRED(S6); SHRED(S7);
    SHRED(Q0); SHRED(Q1); SHRED(Q2); SHRED(Q3);
    SHRED(Q4); SHRED(Q5); SHRED(Q6); SHRED(Q7);
    if (lane == 0) {
        float4* r = &sRed[warp * 16];
        r[0]=S0; r[1]=S1; r[2]=S2; r[3]=S3; r[4]=S4; r[5]=S5; r[6]=S6; r[7]=S7;
        r[8]=Q0; r[9]=Q1; r[10]=Q2; r[11]=Q3; r[12]=Q4; r[13]=Q5; r[14]=Q6; r[15]=Q7;
    }
    __syncthreads();
    if (tid < 64) {
        const float* rf = (const float*)sRed;
        float s = 0.f;
#pragma unroll
        for (int w = 0; w < 8; w++) s += rf[w * 64 + tid];
        atomicAdd(&g_stats[tid], (double)s);
    }
}

// ---------------- K2: finalize layer-0 batchnorm ({mean,rstd} for dice_f) ----------------
__global__ void k_fin0(const float* __restrict__ a0) {
    int c = threadIdx.x;  // 32
    double m = g_stats[c] / NTOT;
    double v = g_stats[32 + c] / NTOT - m * m;
    float rstd = (float)(1.0 / sqrt(v + 1e-9));
    float al = a0[c];
    g_dice0[c] = make_float4((float)m, rstd, al, 1.0f - al);
}

// ---------------- K3: dice0(h0) @ W1 + b1; store fp16 + stats ----------------
#define H1STEP(xs_, d_) { float hd_ = dice_f((xs_), sD0[(d_)]); \
    u64 hdd_ = pack2(hd_, hd_); ulonglong2 w_; \
    w_=sW1_2[(d_)*4+0]; fma2(b0,w_.x,hdd_); fma2(b1,w_.y,hdd_); \
    w_=sW1_2[(d_)*4+1]; fma2(b2,w_.x,hdd_); fma2(b3,w_.y,hdd_); \
    w_=sW1_2[(d_)*4+2]; fma2(b4,w_.x,hdd_); fma2(b5,w_.y,hdd_); \
    w_=sW1_2[(d_)*4+3]; fma2(b6,w_.x,hdd_); fma2(b7,w_.y,hdd_); }
#define H1PAIR(us_, d_) { float2 f_ = upkh(us_); H1STEP(f_.x, d_) H1STEP(f_.y, (d_)+1) }

// grid 2048: 2 chunks each
__global__ void __launch_bounds__(CH, 3) k_h1(const float* __restrict__ W1,
                                              const float* __restrict__ b1) {
    int blk = blockIdx.x;
    int tid = threadIdx.x;
    int lane = tid & 31, warp = tid >> 5;

    __shared__ float4 sW1[C0 * 4];
    __shared__ float4 sB1[4];
    __shared__ float4 sD0[C0];
    __shared__ float4 sRed[8 * 8];

    for (int i = tid; i < C0 * 4; i += CH) sW1[i] = ((const float4*)W1)[i];
    if (tid < 4)  sB1[tid] = ((const float4*)b1)[tid];
    if (tid < C0) sD0[tid] = g_dice0[tid];
    __syncthreads();

    const ulonglong2* sW1_2 = (const ulonglong2*)sW1;
    const ulonglong2* sB1_2 = (const ulonglong2*)sB1;

    u64 s0=0,s1=0,s2=0,s3=0,s4=0,s5=0,s6=0,s7=0;
    u64 q0=0,q1=0,q2=0,q3=0,q4=0,q5=0,q6=0,q7=0;

    const uint4* sbase = &g_h0h[(size_t)blk * 2 * 1024 + warp * 128];

#pragma unroll
    for (int lc = 0; lc < 2; lc++) {
        const uint4* srcb = sbase + (size_t)lc * 1024;
        uint4 xA = __ldcs(&srcb[0*32+lane]);
        uint4 xB = __ldcs(&srcb[1*32+lane]);
        uint4 xC = __ldcs(&srcb[2*32+lane]);
        uint4 xD = __ldcs(&srcb[3*32+lane]);

        u64 b0,b1,b2,b3,b4,b5,b6,b7;
        { ulonglong2 t;
          t=sB1_2[0]; b0=t.x; b1=t.y;  t=sB1_2[1]; b2=t.x; b3=t.y;
          t=sB1_2[2]; b4=t.x; b5=t.y;  t=sB1_2[3]; b6=t.x; b7=t.y; }

        H1PAIR(xA.x, 0)  H1PAIR(xA.y, 2)  H1PAIR(xA.z, 4)  H1PAIR(xA.w, 6)
        H1PAIR(xB.x, 8)  H1PAIR(xB.y,10)  H1PAIR(xB.z,12)  H1PAIR(xB.w,14)
        H1PAIR(xC.x,16)  H1PAIR(xC.y,18)  H1PAIR(xC.z,20)  H1PAIR(xC.w,22)
        H1PAIR(xD.x,24)  H1PAIR(xD.y,26)  H1PAIR(xD.z,28)  H1PAIR(xD.w,30)

        size_t chunk = (size_t)blk * 2 + lc;
        uint4 pA = make_uint4(h2p(b0), h2p(b1), h2p(b2), h2p(b3));
        uint4 pB = make_uint4(h2p(b4), h2p(b5), h2p(b6), h2p(b7));
        uint4* dst = &g_h1h[chunk * 512 + warp * 64];
        __stcs(&dst[0*32+lane], pA); __stcs(&dst[1*32+lane], pB);

        add2(s0,b0); add2(s1,b1); add2(s2,b2); add2(s3,b3);
        add2(s4,b4); add2(s5,b5); add2(s6,b6); add2(s7,b7);
        fma2(q0,b0,b0); fma2(q1,b1,b1); fma2(q2,b2,b2); fma2(q3,b3,b3);
        fma2(q4,b4,b4); fma2(q5,b5,b5); fma2(q6,b6,b6); fma2(q7,b7,b7);
    }

    float4 S0,S1,S2,S3, Q0,Q1,Q2,Q3;
    unpack2(s0,S0.x,S0.y); unpack2(s1,S0.z,S0.w);  unpack2(s2,S1.x,S1.y); unpack2(s3,S1.z,S1.w);
    unpack2(s4,S2.x,S2.y); unpack2(s5,S2.z,S2.w);  unpack2(s6,S3.x,S3.y); unpack2(s7,S3.z,S3.w);
    unpack2(q0,Q0.x,Q0.y); unpack2(q1,Q0.z,Q0.w);  unpack2(q2,Q1.x,Q1.y); unpack2(q3,Q1.z,Q1.w);
    unpack2(q4,Q2.x,Q2.y); unpack2(q5,Q2.z,Q2.w);  unpack2(q6,Q3.x,Q3.y); unpack2(q7,Q3.z,Q3.w);

    SHRED(S0); SHRED(S1); SHRED(S2); SHRED(S3);
    SHRED(Q0); SHRED(Q1); SHRED(Q2); SHRED(Q3);
    if (lane == 0) {
        float4* r = &sRed[warp * 8];
        r[0]=S0; r[1]=S1; r[2]=S2; r[3]=S3;
        r[4]=Q0; r[5]=Q1; r[6]=Q2; r[7]=Q3;
    }
    __syncthreads();
    if (tid < 32) {
        const float* rf = (const float*)sRed;
        float s = 0.f;
#pragma unroll
        for (int w = 0; w < 8; w++) s += rf[w * 32 + tid];
        atomicAdd(&g_stats[64 + tid], (double)s);
    }
}

// ---------------- K5: score = dice1(h1)@wk + bk; out += score*keys (fin1 folded) ----------------
// grid 2048: 4 blocks per batch, 2 chunks each
__global__ void __launch_bounds__(CH, 3) k_out(const float* __restrict__ keys,
                                               const float* __restrict__ wk,
                                               const float* __restrict__ bk,
                                               const float* __restrict__ a1,
                                               float* __restrict__ out) {
    int blk = blockIdx.x;
    int b   = blk >> 2;
    int ck0 = (blk & 3) * 2;
    int tid = threadIdx.x;
    int lane = tid & 31, warp = tid >> 5;

    __shared__ float  sK[CH * 21];
    __shared__ float4 sD1[C1];
    __shared__ float4 sWk4[4];
    __shared__ float  sBk;
    __shared__ float4 sRed[8 * 5];

    if (tid >= 32 && tid < 48) {      // fin1 folded: folded dice constants per block
        int c = tid - 32;
        double m = g_stats[64 + c] / NTOT;
        double v = g_stats[80 + c] / NTOT - m * m;
        float rstd = (float)(1.0 / sqrt(v + 1e-9));
        float al = a1[c];
        sD1[c] = make_float4(-LOG2E * rstd, LOG2E * (float)m * rstd, al, 1.0f - al);
    }
    if (tid < 4)  sWk4[tid] = ((const float4*)wk)[tid];
    if (tid == 0) sBk = bk[0];

    float4 A0=F4Z,A1=F4Z,A2=F4Z,A3=F4Z,A4=F4Z;

    for (int lc = 0; lc < 2; lc++) {
        size_t chunk = (size_t)b * 8 + ck0 + lc;
        const uint4* hb = &g_h1h[chunk * 512 + warp * 64];
        uint4 u0 = __ldcs(&hb[0*32+lane]);
        uint4 u1 = __ldcs(&hb[1*32+lane]);

        __syncthreads();
        stage_keys(sK, keys, chunk, tid);
        __syncthreads();

        float score = sBk;
        {
            float2 f;
            f = upkh(u0.x);
            score = fmaf(dice_fast(f.x, sD1[ 0]), sWk4[0].x, score);
            score = fmaf(dice_fast(f.y, sD1[ 1]), sWk4[0].y, score);
            f = upkh(u0.y);
            score = fmaf(dice_fast(f.x, sD1[ 2]), sWk4[0].z, score);
            score = fmaf(dice_fast(f.y, sD1[ 3]), sWk4[0].w, score);
            f = upkh(u0.z);
            score = fmaf(dice_fast(f.x, sD1[ 4]), sWk4[1].x, score);
            score = fmaf(dice_fast(f.y, sD1[ 5]), sWk4[1].y, score);
            f = upkh(u0.w);
            score = fmaf(dice_fast(f.x, sD1[ 6]), sWk4[1].z, score);
            score = fmaf(dice_fast(f.y, sD1[ 7]), sWk4[1].w, score);
            f = upkh(u1.x);
            score = fmaf(dice_fast(f.x, sD1[ 8]), sWk4[2].x, score);
            score = fmaf(dice_fast(f.y, sD1[ 9]), sWk4[2].y, score);
            f = upkh(u1.y);
            score = fmaf(dice_fast(f.x, sD1[10]), sWk4[2].z, score);
            score = fmaf(dice_fast(f.y, sD1[11]), sWk4[2].w, score);
            f = upkh(u1.z);
            score = fmaf(dice_fast(f.x, sD1[12]), sWk4[3].x, score);
            score = fmaf(dice_fast(f.y, sD1[13]), sWk4[3].y, score);
            f = upkh(u1.w);
            score = fmaf(dice_fast(f.x, sD1[14]), sWk4[3].z, score);
            score = fmaf(dice_fast(f.y, sD1[15]), sWk4[3].w, score);
        }

        const float* kr = &sK[tid * 21];
        A0.x=fmaf(score,kr[0],A0.x);  A0.y=fmaf(score,kr[1],A0.y);
        A0.z=fmaf(score,kr[2],A0.z);  A0.w=fmaf(score,kr[3],A0.w);
        A1.x=fmaf(score,kr[4],A1.x);  A1.y=fmaf(score,kr[5],A1.y);
        A1.z=fmaf(score,kr[6],A1.z);  A1.w=fmaf(score,kr[7],A1.w);
        A2.x=fmaf(score,kr[8],A2.x);  A2.y=fmaf(score,kr[9],A2.y);
        A2.z=fmaf(score,kr[10],A2.z); A2.w=fmaf(score,kr[11],A2.w);
        A3.x=fmaf(score,kr[12],A3.x); A3.y=fmaf(score,kr[13],A3.y);
        A3.z=fmaf(score,kr[14],A3.z); A3.w=fmaf(score,kr[15],A3.w);
        A4.x=fmaf(score,kr[16],A4.x); A4.y=fmaf(score,kr[17],A4.y);
        A4.z=fmaf(score,kr[18],A4.z); A4.w=fmaf(score,kr[19],A4.w);
    }

    SHRED(A0); SHRED(A1); SHRED(A2); SHRED(A3); SHRED(A4);
    if (lane == 0) {
        float4* r = &sRed[warp * 5];
        r[0]=A0; r[1]=A1; r[2]=A2; r[3]=A3; r[4]=A4;
    }
    __syncthreads();
    if (tid < DD) {
        const float* rf = (const float*)sRed;
        float s = 0.f;
#pragma unroll
        for (int w = 0; w < 8; w++) s += rf[w * 20 + tid];
        atomicAdd(&out[b * DD + tid], s);
    }
}

// ---------------- launch ----------------
extern "C" void kernel_launch(void* const* d_in, const int* in_sizes, int n_in,
                              void* d_out, int out_size) {
    const float* keys = (const float*)d_in[0];
    const float* q    = (const float*)d_in[1];
    /* d_in[2] = mask: dead in the reference (unmasked scores are used) */
    const float* W0   = (const float*)d_in[3];
    const float* b0   = (const float*)d_in[4];
    const float* a0   = (const float*)d_in[5];
    const float* W1   = (const float*)d_in[6];
    const float* b1   = (const float*)d_in[7];
    const float* a1   = (const float*)d_in[8];
    const float* wk   = (const float*)d_in[9];
    const float* bk   = (const float*)d_in[10];
    float* out = (float*)d_out;

    k_prep<<<BB, 32>>>(q, W0, b0, out);
    k_h0  <<<2048, CH>>>(keys);
    k_fin0<<<1, 32>>>(a0);
    k_h1  <<<2048, CH>>>(W1, b1);
    k_out <<<2048, CH>>>(keys, wk, bk, a1, out);
}

// round 12
// speedup vs baseline: 1.6128x; 1.6128x over previous
#include <cuda_runtime.h>
#include <cuda_fp16.h>
#include <math.h>
#include <stdint.h>

#define BB 512
#define TT 2048
#define DD 20
#define C0 32
#define C1 16
#define CH 256
#define NCHUNK ((BB*TT)/CH)     /* 4096 */
#define NTOT   ((double)(BB)*(double)(TT))

typedef unsigned long long u64;

// ---------------- scratch (device globals; no allocation) ----------------
__device__ uint4  g_h0h[(size_t)NCHUNK * 8 * 4 * 32];  // fp16 h0, 67MB
__device__ uint4  g_h1h[(size_t)NCHUNK * 8 * 2 * 32];  // fp16 h1, 33.5MB
__device__ float  g_Weff[BB * DD * C0];            // [b][d][c]
__device__ float  g_Cb[BB * C0];                   // [b][c]
__device__ double g_stats[96];                     // [0:32) s0 [32:64) q0 [64:80) s1 [80:96) q1
__device__ float4 g_dice0[C0];                     // {mean, rstd, alpha, 1-alpha} (for dice_f)

#define F4Z make_float4(0.f,0.f,0.f,0.f)
#define SHRED(vv_) {for(int o_=16;o_>0;o_>>=1){vv_.x+=__shfl_xor_sync(0xffffffffu,vv_.x,o_);vv_.y+=__shfl_xor_sync(0xffffffffu,vv_.y,o_);vv_.z+=__shfl_xor_sync(0xffffffffu,vv_.z,o_);vv_.w+=__shfl_xor_sync(0xffffffffu,vv_.w,o_);}}

// ---- packed f32x2 primitives ----
__device__ __forceinline__ u64 pack2(float lo, float hi) {
    u64 r; asm("mov.b64 %0, {%1, %2};" : "=l"(r) : "f"(lo), "f"(hi)); return r;
}
__device__ __forceinline__ void unpack2(u64 v, float& lo, float& hi) {
    asm("mov.b64 {%0, %1}, %2;" : "=f"(lo), "=f"(hi) : "l"(v));
}
__device__ __forceinline__ void fma2(u64& acc, u64 a, u64 b) {
    asm("fma.rn.f32x2 %0, %1, %2, %0;" : "+l"(acc) : "l"(a), "l"(b));
}
__device__ __forceinline__ void add2(u64& acc, u64 a) {
    asm("add.rn.f32x2 %0, %1, %0;" : "+l"(acc) : "l"(a));
}
__device__ __forceinline__ uint32_t h2p(u64 v) {
    float lo, hi; unpack2(v, lo, hi);
    union { __half2 h; uint32_t u; } cv;
    cv.h = __floats2half2_rn(lo, hi);
    return cv.u;
}
__device__ __forceinline__ float2 upkh(uint32_t u) {
    union { __half2 h; uint32_t u; } cv;
    cv.u = u;
    return __half22float2(cv.h);
}

// classic dice (proven in k_h1): pr = {mean, rstd, alpha, 1-alpha}
__device__ __forceinline__ float dice_f(float x, float4 pr) {
    float xn = (x - pr.x) * pr.y;
    float p  = 1.0f / (1.0f + __expf(-xn));
    return x * (pr.z + p * pr.w);
}

// folded fast dice (proven in k_out): pr = {c1, c0, alpha, 1-alpha}
__device__ __forceinline__ float dice_fast(float x, float4 pr) {
    float t = fmaf(x, pr.x, pr.y);
    float e; asm("ex2.approx.f32 %0, %1;" : "=f"(e) : "f"(t));
    float d = 1.0f + e;
    float p; asm("rcp.approx.f32 %0, %1;" : "=f"(p) : "f"(d));
    return x * fmaf(p, pr.w, pr.z);
}

#define LOG2E 1.442695040888963f

// stage one 256x20 key chunk into padded smem (row stride 21 -> conflict-free)
__device__ __forceinline__ void stage_keys(float* sK, const float* __restrict__ keys,
                                           size_t chunk, int tid) {
    const float4* src = (const float4*)(keys + chunk * (size_t)(CH * DD));
#pragma unroll
    for (int i = 0; i < 5; i++) {
        float4 t = src[tid + i * CH];
        int f = tid + i * CH;
        int r = f / 5;
        int c = (f - r * 5) * 4;
        float* p = &sK[r * 21 + c];
        p[0] = t.x; p[1] = t.y; p[2] = t.z; p[3] = t.w;
    }
}

// ---------------- K0: per-batch folded weights + zero accumulators ----------------
__global__ void k_prep(const float* __restrict__ q, const float* __restrict__ W0,
                       const float* __restrict__ b0, float* __restrict__ out) {
    int b = blockIdx.x;
    int c = threadIdx.x;              // 32 threads
    if (b == 0) {
        for (int i = c; i < 96; i += 32) g_stats[i] = 0.0;
    }
    int gid = b * 32 + c;
    if (gid < BB * DD) out[gid] = 0.0f;

    float acc = b0[c];
#pragma unroll
    for (int d = 0; d < DD; d++) {
        float qd = q[b * DD + d];
        float wA = W0[(d)          * C0 + c];
        float wB = W0[(DD + d)     * C0 + c];
        float wC = W0[(2 * DD + d) * C0 + c];
        float wD = W0[(3 * DD + d) * C0 + c];
        g_Weff[(b * DD + d) * C0 + c] = wB - wC + qd * wD;
        acc += qd * (wA + wC);
    }
    g_Cb[b * C0 + c] = acc;
}

// ---------------- K1: h0 = keys @ Weff[b] + Cb[b]; store fp16 + stats (R10 exact) ----------------
__global__ void __launch_bounds__(CH, 2) k_h0(const float* __restrict__ keys) {
    int blk = blockIdx.x;             // 1024 blocks: 2 per batch, 4 chunks each
    int b   = blk >> 1;
    int ck0 = (blk & 1) * 4;
    int tid = threadIdx.x;
    int lane = tid & 31, warp = tid >> 5;

    __shared__ float4 sW[DD * 8];
    __shared__ float4 sC[8];
    __shared__ float  sK[CH * 21];
    __shared__ float4 sRed[8 * 16];

    for (int i = tid; i < DD * 8; i += CH)
        sW[i] = ((const float4*)(&g_Weff[b * DD * C0]))[i];
    if (tid < 8)
        sC[tid] = ((const float4*)(&g_Cb[b * C0]))[tid];

    const ulonglong2* sW2 = (const ulonglong2*)sW;
    const ulonglong2* sC2 = (const ulonglong2*)sC;

    u64 s0=0,s1=0,s2=0,s3=0,s4=0,s5=0,s6=0,s7=0,s8=0,s9=0,s10=0,s11=0,s12=0,s13=0,s14=0,s15=0;
    u64 q0=0,q1=0,q2=0,q3=0,q4=0,q5=0,q6=0,q7=0,q8=0,q9=0,q10=0,q11=0,q12=0,q13=0,q14=0,q15=0;

    for (int lc = 0; lc < 4; lc++) {
        size_t chunk = (size_t)b * 8 + ck0 + lc;
        __syncthreads();
        stage_keys(sK, keys, chunk, tid);
        __syncthreads();

        u64 a0,a1,a2,a3,a4,a5,a6,a7,a8,a9,a10,a11,a12,a13,a14,a15;
        { ulonglong2 t;
          t=sC2[0]; a0 =t.x; a1 =t.y;  t=sC2[1]; a2 =t.x; a3 =t.y;
          t=sC2[2]; a4 =t.x; a5 =t.y;  t=sC2[3]; a6 =t.x; a7 =t.y;
          t=sC2[4]; a8 =t.x; a9 =t.y;  t=sC2[5]; a10=t.x; a11=t.y;
          t=sC2[6]; a12=t.x; a13=t.y;  t=sC2[7]; a14=t.x; a15=t.y; }

#pragma unroll
        for (int d = 0; d < DD; d++) {
            float kd = sK[tid * 21 + d];
            u64 kdd = pack2(kd, kd);
            ulonglong2 w;
            w=sW2[d*8+0]; fma2(a0 ,w.x,kdd); fma2(a1 ,w.y,kdd);
            w=sW2[d*8+1]; fma2(a2 ,w.x,kdd); fma2(a3 ,w.y,kdd);
            w=sW2[d*8+2]; fma2(a4 ,w.x,kdd); fma2(a5 ,w.y,kdd);
            w=sW2[d*8+3]; fma2(a6 ,w.x,kdd); fma2(a7 ,w.y,kdd);
            w=sW2[d*8+4]; fma2(a8 ,w.x,kdd); fma2(a9 ,w.y,kdd);
            w=sW2[d*8+5]; fma2(a10,w.x,kdd); fma2(a11,w.y,kdd);
            w=sW2[d*8+6]; fma2(a12,w.x,kdd); fma2(a13,w.y,kdd);
            w=sW2[d*8+7]; fma2(a14,w.x,kdd); fma2(a15,w.y,kdd);
        }
        uint4 p0 = make_uint4(h2p(a0), h2p(a1), h2p(a2), h2p(a3));
        uint4 p1 = make_uint4(h2p(a4), h2p(a5), h2p(a6), h2p(a7));
        uint4 p2 = make_uint4(h2p(a8), h2p(a9), h2p(a10), h2p(a11));
        uint4 p3 = make_uint4(h2p(a12), h2p(a13), h2p(a14), h2p(a15));
        uint4* dst = &g_h0h[chunk * 1024 + warp * 128];
        __stcs(&dst[0*32+lane], p0); __stcs(&dst[1*32+lane], p1);
        __stcs(&dst[2*32+lane], p2); __stcs(&dst[3*32+lane], p3);

        add2(s0,a0); add2(s1,a1); add2(s2,a2); add2(s3,a3);
        add2(s4,a4); add2(s5,a5); add2(s6,a6); add2(s7,a7);
        add2(s8,a8); add2(s9,a9); add2(s10,a10); add2(s11,a11);
        add2(s12,a12); add2(s13,a13); add2(s14,a14); add2(s15,a15);
        fma2(q0,a0,a0); fma2(q1,a1,a1); fma2(q2,a2,a2); fma2(q3,a3,a3);
        fma2(q4,a4,a4); fma2(q5,a5,a5); fma2(q6,a6,a6); fma2(q7,a7,a7);
        fma2(q8,a8,a8); fma2(q9,a9,a9); fma2(q10,a10,a10); fma2(q11,a11,a11);
        fma2(q12,a12,a12); fma2(q13,a13,a13); fma2(q14,a14,a14); fma2(q15,a15,a15);
    }

    float4 S0,S1,S2,S3,S4,S5,S6,S7, Q0,Q1,Q2,Q3,Q4,Q5,Q6,Q7;
    unpack2(s0,S0.x,S0.y); unpack2(s1,S0.z,S0.w);  unpack2(s2,S1.x,S1.y); unpack2(s3,S1.z,S1.w);
    unpack2(s4,S2.x,S2.y); unpack2(s5,S2.z,S2.w);  unpack2(s6,S3.x,S3.y); unpack2(s7,S3.z,S3.w);
    unpack2(s8,S4.x,S4.y); unpack2(s9,S4.z,S4.w);  unpack2(s10,S5.x,S5.y); unpack2(s11,S5.z,S5.w);
    unpack2(s12,S6.x,S6.y); unpack2(s13,S6.z,S6.w); unpack2(s14,S7.x,S7.y); unpack2(s15,S7.z,S7.w);
    unpack2(q0,Q0.x,Q0.y); unpack2(q1,Q0.z,Q0.w);  unpack2(q2,Q1.x,Q1.y); unpack2(q3,Q1.z,Q1.w);
    unpack2(q4,Q2.x,Q2.y); unpack2(q5,Q2.z,Q2.w);  unpack2(q6,Q3.x,Q3.y); unpack2(q7,Q3.z,Q3.w);
    unpack2(q8,Q4.x,Q4.y); unpack2(q9,Q4.z,Q4.w);  unpack2(q10,Q5.x,Q5.y); unpack2(q11,Q5.z,Q5.w);
    unpack2(q12,Q6.x,Q6.y); unpack2(q13,Q6.z,Q6.w); unpack2(q14,Q7.x,Q7.y); unpack2(q15,Q7.z,Q7.w);

    SHRED(S0); SHRED(S1); SHRED(S2); SHRED(S3);
    SHRED(S4); SHRED(S5); SHRED(S6); SHRED(S7);
    SHRED(Q0); SHRED(Q1); SHRED(Q2); SHRED(Q3);
    SHRED(Q4); SHRED(Q5); SHRED(Q6); SHRED(Q7);
    if (lane == 0) {
        float4* r = &sRed[warp * 16];
        r[0]=S0; r[1]=S1; r[2]=S2; r[3]=S3; r[4]=S4; r[5]=S5; r[6]=S6; r[7]=S7;
        r[8]=Q0; r[9]=Q1; r[10]=Q2; r[11]=Q3; r[12]=Q4; r[13]=Q5; r[14]=Q6; r[15]=Q7;
    }
    __syncthreads();
    if (tid < 64) {
        const float* rf = (const float*)sRed;
        float s = 0.f;
#pragma unroll
        for (int w = 0; w < 8; w++) s += rf[w * 64 + tid];
        atomicAdd(&g_stats[tid], (double)s);
    }
}

// ---------------- K2: finalize layer-0 batchnorm ({mean,rstd} for dice_f) ----------------
__global__ void k_fin0(const float* __restrict__ a0) {
    int c = threadIdx.x;  // 32
    double m = g_stats[c] / NTOT;
    double v = g_stats[32 + c] / NTOT - m * m;
    float rstd = (float)(1.0 / sqrt(v + 1e-9));
    float al = a0[c];
    g_dice0[c] = make_float4((float)m, rstd, al, 1.0f - al);
}

// ---------------- K3: dice0(h0) @ W1 + b1; TWO rows per thread (halved weight LDS) ----------------
#define H2STEP(xa_, xb_, d_) { \
    float4 pr_ = sD0[(d_)]; \
    float hA_ = dice_f((xa_), pr_); float hB_ = dice_f((xb_), pr_); \
    u64 hA2_ = pack2(hA_, hA_); u64 hB2_ = pack2(hB_, hB_); ulonglong2 w_; \
    w_=sW1_2[(d_)*4+0]; fma2(cA0,w_.x,hA2_); fma2(cB0,w_.x,hB2_); fma2(cA1,w_.y,hA2_); fma2(cB1,w_.y,hB2_); \
    w_=sW1_2[(d_)*4+1]; fma2(cA2,w_.x,hA2_); fma2(cB2,w_.x,hB2_); fma2(cA3,w_.y,hA2_); fma2(cB3,w_.y,hB2_); \
    w_=sW1_2[(d_)*4+2]; fma2(cA4,w_.x,hA2_); fma2(cB4,w_.x,hB2_); fma2(cA5,w_.y,hA2_); fma2(cB5,w_.y,hB2_); \
    w_=sW1_2[(d_)*4+3]; fma2(cA6,w_.x,hA2_); fma2(cB6,w_.x,hB2_); fma2(cA7,w_.y,hA2_); fma2(cB7,w_.y,hB2_); }
#define H2PAIR(ua_, ub_, d_) { \
    float2 fa_ = upkh(ua_); float2 fb_ = upkh(ub_); \
    H2STEP(fa_.x, fb_.x, d_) H2STEP(fa_.y, fb_.y, (d_)+1) }

__global__ void __launch_bounds__(CH, 2) k_h1(const float* __restrict__ W1,
                                              const float* __restrict__ b1) {
    int blk = blockIdx.x;             // 1024 blocks x 4 chunks = 2 chunk-pairs
    int tid = threadIdx.x;
    int lane = tid & 31, warp = tid >> 5;

    __shared__ float4 sW1[C0 * 4];
    __shared__ float4 sB1[4];
    __shared__ float4 sD0[C0];
    __shared__ float4 sRed[8 * 8];

    for (int i = tid; i < C0 * 4; i += CH) sW1[i] = ((const float4*)W1)[i];
    if (tid < 4)  sB1[tid] = ((const float4*)b1)[tid];
    if (tid < C0) sD0[tid] = g_dice0[tid];
    __syncthreads();

    const ulonglong2* sW1_2 = (const ulonglong2*)sW1;
    const ulonglong2* sB1_2 = (const ulonglong2*)sB1;

    u64 s0=0,s1=0,s2=0,s3=0,s4=0,s5=0,s6=0,s7=0;
    u64 q0=0,q1=0,q2=0,q3=0,q4=0,q5=0,q6=0,q7=0;

    const uint4* sbase = &g_h0h[(size_t)blk * 4 * 1024 + warp * 128];

#pragma unroll
    for (int lp = 0; lp < 2; lp++) {
        const uint4* c0 = sbase + (size_t)(2*lp)   * 1024;
        const uint4* c1 = sbase + (size_t)(2*lp+1) * 1024;
        uint4 xA = __ldcs(&c0[0*32+lane]);
        uint4 xB = __ldcs(&c0[1*32+lane]);
        uint4 xC = __ldcs(&c0[2*32+lane]);
        uint4 xD = __ldcs(&c0[3*32+lane]);
        uint4 yA = __ldcs(&c1[0*32+lane]);
        uint4 yB = __ldcs(&c1[1*32+lane]);
        uint4 yC = __ldcs(&c1[2*32+lane]);
        uint4 yD = __ldcs(&c1[3*32+lane]);

        u64 cA0,cA1,cA2,cA3,cA4,cA5,cA6,cA7, cB0,cB1,cB2,cB3,cB4,cB5,cB6,cB7;
        { ulonglong2 t;
          t=sB1_2[0]; cA0=t.x; cA1=t.y; cB0=t.x; cB1=t.y;
          t=sB1_2[1]; cA2=t.x; cA3=t.y; cB2=t.x; cB3=t.y;
          t=sB1_2[2]; cA4=t.x; cA5=t.y; cB4=t.x; cB5=t.y;
          t=sB1_2[3]; cA6=t.x; cA7=t.y; cB6=t.x; cB7=t.y; }

        H2PAIR(xA.x, yA.x, 0)  H2PAIR(xA.y, yA.y, 2)  H2PAIR(xA.z, yA.z, 4)  H2PAIR(xA.w, yA.w, 6)
        H2PAIR(xB.x, yB.x, 8)  H2PAIR(xB.y, yB.y,10)  H2PAIR(xB.z, yB.z,12)  H2PAIR(xB.w, yB.w,14)
        H2PAIR(xC.x, yC.x,16)  H2PAIR(xC.y, yC.y,18)  H2PAIR(xC.z, yC.z,20)  H2PAIR(xC.w, yC.w,22)
        H2PAIR(xD.x, yD.x,24)  H2PAIR(xD.y, yD.y,26)  H2PAIR(xD.z, yD.z,28)  H2PAIR(xD.w, yD.w,30)

        size_t chunkA = (size_t)blk * 4 + 2*lp;
        uint4 pA = make_uint4(h2p(cA0), h2p(cA1), h2p(cA2), h2p(cA3));
        uint4 pB = make_uint4(h2p(cA4), h2p(cA5), h2p(cA6), h2p(cA7));
        uint4* dstA = &g_h1h[chunkA * 512 + warp * 64];
        __stcs(&dstA[0*32+lane], pA); __stcs(&dstA[1*32+lane], pB);
        uint4 pC = make_uint4(h2p(cB0), h2p(cB1), h2p(cB2), h2p(cB3));
        uint4 pD = make_uint4(h2p(cB4), h2p(cB5), h2p(cB6), h2p(cB7));
        uint4* dstB = &g_h1h[(chunkA + 1) * 512 + warp * 64];
        __stcs(&dstB[0*32+lane], pC); __stcs(&dstB[1*32+lane], pD);

        add2(s0,cA0); add2(s1,cA1); add2(s2,cA2); add2(s3,cA3);
        add2(s4,cA4); add2(s5,cA5); add2(s6,cA6); add2(s7,cA7);
        add2(s0,cB0); add2(s1,cB1); add2(s2,cB2); add2(s3,cB3);
        add2(s4,cB4); add2(s5,cB5); add2(s6,cB6); add2(s7,cB7);
        fma2(q0,cA0,cA0); fma2(q1,cA1,cA1); fma2(q2,cA2,cA2); fma2(q3,cA3,cA3);
        fma2(q4,cA4,cA4); fma2(q5,cA5,cA5); fma2(q6,cA6,cA6); fma2(q7,cA7,cA7);
        fma2(q0,cB0,cB0); fma2(q1,cB1,cB1); fma2(q2,cB2,cB2); fma2(q3,cB3,cB3);
        fma2(q4,cB4,cB4); fma2(q5,cB5,cB5); fma2(q6,cB6,cB6); fma2(q7,cB7,cB7);
    }

    float4 S0,S1,S2,S3, Q0,Q1,Q2,Q3;
    unpack2(s0,S0.x,S0.y); unpack2(s1,S0.z,S0.w);  unpack2(s2,S1.x,S1.y); unpack2(s3,S1.z,S1.w);
    unpack2(s4,S2.x,S2.y); unpack2(s5,S2.z,S2.w);  unpack2(s6,S3.x,S3.y); unpack2(s7,S3.z,S3.w);
    unpack2(q0,Q0.x,Q0.y); unpack2(q1,Q0.z,Q0.w);  unpack2(q2,Q1.x,Q1.y); unpack2(q3,Q1.z,Q1.w);
    unpack2(q4,Q2.x,Q2.y); unpack2(q5,Q2.z,Q2.w);  unpack2(q6,Q3.x,Q3.y); unpack2(q7,Q3.z,Q3.w);

    SHRED(S0); SHRED(S1); SHRED(S2); SHRED(S3);
    SHRED(Q0); SHRED(Q1); SHRED(Q2); SHRED(Q3);
    if (lane == 0) {
        float4* r = &sRed[warp * 8];
        r[0]=S0; r[1]=S1; r[2]=S2; r[3]=S3;
        r[4]=Q0; r[5]=Q1; r[6]=Q2; r[7]=Q3;
    }
    __syncthreads();
    if (tid < 32) {
        const float* rf = (const float*)sRed;
        float s = 0.f;
#pragma unroll
        for (int w = 0; w < 8; w++) s += rf[w * 32 + tid];
        atomicAdd(&g_stats[64 + tid], (double)s);
    }
}

// ---------------- K5: score = dice1(h1)@wk + bk; out += score*keys (R10 exact) ----------------
__global__ void __launch_bounds__(CH) k_out(const float* __restrict__ keys,
                                            const float* __restrict__ wk,
                                            const float* __restrict__ bk,
                                            const float* __restrict__ a1,
                                            float* __restrict__ out) {
    int blk = blockIdx.x;             // 1024: 2 blocks per batch
    int b   = blk >> 1;
    int ck0 = (blk & 1) * 4;
    int tid = threadIdx.x;
    int lane = tid & 31, warp = tid >> 5;

    __shared__ float  sK[CH * 21];
    __shared__ float4 sD1[C1];
    __shared__ float4 sWk4[4];
    __shared__ float  sBk;
    __shared__ float4 sRed[8 * 5];

    if (tid >= 32 && tid < 48) {
        int c = tid - 32;
        double m = g_stats[64 + c] / NTOT;
        double v = g_stats[80 + c] / NTOT - m * m;
        float rstd = (float)(1.0 / sqrt(v + 1e-9));
        float al = a1[c];
        sD1[c] = make_float4(-LOG2E * rstd, LOG2E * (float)m * rstd, al, 1.0f - al);
    }
    if (tid < 4)  sWk4[tid] = ((const float4*)wk)[tid];
    if (tid == 0) sBk = bk[0];

    float4 A0=F4Z,A1=F4Z,A2=F4Z,A3=F4Z,A4=F4Z;

    for (int lc = 0; lc < 4; lc++) {
        size_t chunk = (size_t)b * 8 + ck0 + lc;
        const uint4* hb = &g_h1h[chunk * 512 + warp * 64];
        uint4 u0 = __ldcs(&hb[0*32+lane]);
        uint4 u1 = __ldcs(&hb[1*32+lane]);

        __syncthreads();
        stage_keys(sK, keys, chunk, tid);
        __syncthreads();

        float score = sBk;
        {
            float2 f;
            f = upkh(u0.x);
            score = fmaf(dice_fast(f.x, sD1[ 0]), sWk4[0].x, score);
            score = fmaf(dice_fast(f.y, sD1[ 1]), sWk4[0].y, score);
            f = upkh(u0.y);
            score = fmaf(dice_fast(f.x, sD1[ 2]), sWk4[0].z, score);
            score = fmaf(dice_fast(f.y, sD1[ 3]), sWk4[0].w, score);
            f = upkh(u0.z);
            score = fmaf(dice_fast(f.x, sD1[ 4]), sWk4[1].x, score);
            score = fmaf(dice_fast(f.y, sD1[ 5]), sWk4[1].y, score);
            f = upkh(u0.w);
            score = fmaf(dice_fast(f.x, sD1[ 6]), sWk4[1].z, score);
            score = fmaf(dice_fast(f.y, sD1[ 7]), sWk4[1].w, score);
            f = upkh(u1.x);
            score = fmaf(dice_fast(f.x, sD1[ 8]), sWk4[2].x, score);
            score = fmaf(dice_fast(f.y, sD1[ 9]), sWk4[2].y, score);
            f = upkh(u1.y);
            score = fmaf(dice_fast(f.x, sD1[10]), sWk4[2].z, score);
            score = fmaf(dice_fast(f.y, sD1[11]), sWk4[2].w, score);
            f = upkh(u1.z);
            score = fmaf(dice_fast(f.x, sD1[12]), sWk4[3].x, score);
            score = fmaf(dice_fast(f.y, sD1[13]), sWk4[3].y, score);
            f = upkh(u1.w);
            score = fmaf(dice_fast(f.x, sD1[14]), sWk4[3].z, score);
            score = fmaf(dice_fast(f.y, sD1[15]), sWk4[3].w, score);
        }

        const float* kr = &sK[tid * 21];
        A0.x=fmaf(score,kr[0],A0.x);  A0.y=fmaf(score,kr[1],A0.y);
        A0.z=fmaf(score,kr[2],A0.z);  A0.w=fmaf(score,kr[3],A0.w);
        A1.x=fmaf(score,kr[4],A1.x);  A1.y=fmaf(score,kr[5],A1.y);
        A1.z=fmaf(score,kr[6],A1.z);  A1.w=fmaf(score,kr[7],A1.w);
        A2.x=fmaf(score,kr[8],A2.x);  A2.y=fmaf(score,kr[9],A2.y);
        A2.z=fmaf(score,kr[10],A2.z); A2.w=fmaf(score,kr[11],A2.w);
        A3.x=fmaf(score,kr[12],A3.x); A3.y=fmaf(score,kr[13],A3.y);
        A3.z=fmaf(score,kr[14],A3.z); A3.w=fmaf(score,kr[15],A3.w);
        A4.x=fmaf(score,kr[16],A4.x); A4.y=fmaf(score,kr[17],A4.y);
        A4.z=fmaf(score,kr[18],A4.z); A4.w=fmaf(score,kr[19],A4.w);
    }

    SHRED(A0); SHRED(A1); SHRED(A2); SHRED(A3); SHRED(A4);
    if (lane == 0) {
        float4* r = &sRed[warp * 5];
        r[0]=A0; r[1]=A1; r[2]=A2; r[3]=A3; r[4]=A4;
    }
    __syncthreads();
    if (tid < DD) {
        const float* rf = (const float*)sRed;
        float s = 0.f;
#pragma unroll
        for (int w = 0; w < 8; w++) s += rf[w * 20 + tid];
        atomicAdd(&out[b * DD + tid], s);
    }
}

// ---------------- launch ----------------
extern "C" void kernel_launch(void* const* d_in, const int* in_sizes, int n_in,
                              void* d_out, int out_size) {
    const float* keys = (const float*)d_in[0];
    const float* q    = (const float*)d_in[1];
    /* d_in[2] = mask: dead in the reference (unmasked scores are used) */
    const float* W0   = (const float*)d_in[3];
    const float* b0   = (const float*)d_in[4];
    const float* a0   = (const float*)d_in[5];
    const float* W1   = (const float*)d_in[6];
    const float* b1   = (const float*)d_in[7];
    const float* a1   = (const float*)d_in[8];
    const float* wk   = (const float*)d_in[9];
    const float* bk   = (const float*)d_in[10];
    float* out = (float*)d_out;

    k_prep<<<BB, 32>>>(q, W0, b0, out);
    k_h0  <<<1024, CH>>>(keys);
    k_fin0<<<1, 32>>>(a0);
    k_h1  <<<1024, CH>>>(W1, b1);
    k_out <<<1024, CH>>>(keys, wk, bk, a1, out);
}